// round 6
// baseline (speedup 1.0000x reference)
#include <cuda_runtime.h>
#include <cuda_fp16.h>
#include <cuda_bf16.h>

// Problem constants
#define Bn 4
#define Cn 64
#define Hn 96
#define Wn 96
#define PLANE (Hn*Wn)            // 9216
#define NPLANES (Bn*Cn)          // 256
#define NTOT (NPLANES*PLANE)     // 2359296
#define CNT_PER_CH (Bn*PLANE)    // 36864
#define BN_EPS 1e-5f
#define NPART 36                 // partial sums per channel: Bn * 9 tiles
#define GRIDP 576                // persistent grid (<= 4 blocks/SM x 144 SMs)
#define TILES_PER_BLOCK 4        // 2304 / 576

// Scratch (__device__ globals; allocation-free rule)
__device__ float    g_psum[Cn * NPART];
__device__ float    g_psq [Cn * NPART];
__device__ unsigned g_count = 0;   // grid barrier arrival counter
__device__ unsigned g_sense = 0;   // grid barrier sense (flips each launch)

// transform: silu(x) and packed spline coordinate mu = m + u
__device__ __forceinline__ float2 kan_transform(float x) {
    float s = __fdividef(x, 1.0f + __expf(-x));   // silu
    float mu = (x + 2.2f) * 2.5f;                 // (x - t0)/h, t0=-2.2, h=0.4
    if (!(mu >= 0.0f && mu < 11.0f)) mu = 11.0f;  // sentinel row -> zero coeffs
    return make_float2(s, mu);
}

// ---------------------------------------------------------------------------
// Single persistent kernel: KAN depthwise conv (4 tiles/block, y kept in
// smem) -> race-free partial stats -> software grid barrier -> BN + ReLU.
// ---------------------------------------------------------------------------
__global__ __launch_bounds__(256, 4)
void kan_fused_kernel(const float* __restrict__ x,
                      const float* __restrict__ base_weight,    // (9)
                      const float* __restrict__ spline_weight,  // (9,8)
                      const float* __restrict__ spline_scaler,  // (9)
                      const float* __restrict__ gamma,
                      const float* __restrict__ beta,
                      float* __restrict__ out)
{
    __shared__ __align__(16) float s_y[TILES_PER_BLOCK][1024];  // y tiles, live across barrier
    __shared__ float2 s_t[34 * 35];                  // (silu, mu) halo tile
    __shared__ uint2  s_coef[12 * 9];                // fp16x4 cubic coeffs
    __shared__ float  s_bw[12];
    __shared__ float  s_rs[8], s_rq[8];
    __shared__ float2 s_bn[TILES_PER_BLOCK];         // (scl, sh) per tile

    const int tid = threadIdx.x;
    const int bid = blockIdx.x;
    const int tx  = tid & 31;
    const int tyb = tid >> 5;

    // ---- build coefficient table (uniform cubic B-spline, closed form) ----
    if (tid < 108) {
        const int m = tid / 9, k = tid % 9;
        float c0 = 0.f, c1 = 0.f, c2 = 0.f, c3 = 0.f;
        if (m < 11) {
            const float F[4][4] = {
                {1.f, -3.f,  3.f, -1.f},   // N_{m-3}
                {4.f,  0.f, -6.f,  3.f},   // N_{m-2}
                {1.f,  3.f,  3.f, -3.f},   // N_{m-1}
                {0.f,  0.f,  0.f,  1.f}    // N_{m}
            };
            const float sc = spline_scaler[k];
            #pragma unroll
            for (int r = 0; r < 4; r++) {
                int j = m - 3 + r;
                if (j >= 0 && j < 8) {
                    float w = spline_weight[k * 8 + j] * sc;
                    c0 += w * F[r][0]; c1 += w * F[r][1];
                    c2 += w * F[r][2]; c3 += w * F[r][3];
                }
            }
        }
        const float inv6 = 1.0f / 6.0f;
        __half2 h01 = __floats2half2_rn(c0 * inv6, c1 * inv6);
        __half2 h23 = __floats2half2_rn(c2 * inv6, c3 * inv6);
        uint2 w;
        w.x = *reinterpret_cast<unsigned*>(&h01);
        w.y = *reinterpret_cast<unsigned*>(&h23);
        s_coef[m * 9 + k] = w;
    }
    if (tid < 9) s_bw[tid] = base_weight[tid];

    // ======================= phase 1: conv over 4 tiles =====================
    #pragma unroll
    for (int it = 0; it < TILES_PER_BLOCK; it++) {
        const int tidx  = bid + it * GRIDP;          // global tile id 0..2303
        const int plane = tidx / 9;
        const int tq    = tidx % 9;
        const int ty0   = (tq / 3) * 32;
        const int tx0   = (tq % 3) * 32;

        if (it) __syncthreads();                     // protect s_t reuse

        // load + transform halo tile (34x34), zero-padded outside plane
        const float* xp = x + plane * PLANE;
        for (int i = tid; i < 34 * 34; i += 256) {
            int hy = i / 34, hx = i % 34;
            int gy = ty0 + hy - 1, gx = tx0 + hx - 1;
            float v = (gy >= 0 && gy < Hn && gx >= 0 && gx < Wn) ? xp[gy * Wn + gx] : 0.0f;
            s_t[hy * 35 + hx] = kan_transform(v);
        }
        __syncthreads();

        float lsum = 0.f, lsq = 0.f;
        #pragma unroll
        for (int r = 0; r < 4; r++) {
            const int oy = tyb + r * 8;
            float acc = 0.f;
            #pragma unroll
            for (int dy = 0; dy < 3; dy++) {
                #pragma unroll
                for (int dx = 0; dx < 3; dx++) {
                    const int k = dy * 3 + dx;
                    float2 t = s_t[(oy + dy) * 35 + (tx + dx)];
                    int   m = (int)t.y;
                    float u = t.y - (float)m;
                    uint2 cw = s_coef[m * 9 + k];
                    float2 c01 = __half22float2(*reinterpret_cast<__half2*>(&cw.x));
                    float2 c23 = __half22float2(*reinterpret_cast<__half2*>(&cw.y));
                    float poly = fmaf(u, fmaf(u, fmaf(u, c23.y, c23.x), c01.y), c01.x);
                    acc += poly + s_bw[k] * t.x;
                }
            }
            s_y[it][oy * 32 + tx] = acc;
            lsum += acc;
            lsq  = fmaf(acc, acc, lsq);
        }

        // block reduction -> race-free partial slot
        #pragma unroll
        for (int o = 16; o > 0; o >>= 1) {
            lsum += __shfl_down_sync(0xffffffffu, lsum, o);
            lsq  += __shfl_down_sync(0xffffffffu, lsq,  o);
        }
        if (tx == 0) { s_rs[tyb] = lsum; s_rq[tyb] = lsq; }
        __syncthreads();
        if (tid == 0) {
            float s = 0.f, q = 0.f;
            #pragma unroll
            for (int i = 0; i < 8; i++) { s += s_rs[i]; q += s_rq[i]; }
            const int c = plane & (Cn - 1);
            const int b = plane >> 6;
            g_psum[c * NPART + b * 9 + tq] = s;
            g_psq [c * NPART + b * 9 + tq] = q;
        }
    }

    // ======================= software grid barrier ==========================
    __syncthreads();
    if (tid == 0) {
        __threadfence();                              // publish partials
        unsigned snap = *(volatile unsigned*)&g_sense;
        unsigned old  = atomicAdd(&g_count, 1u);
        if (old == GRIDP - 1) {
            *(volatile unsigned*)&g_count = 0u;       // reset for next launch
            __threadfence();
            atomicExch(&g_sense, snap ^ 1u);          // release
        } else {
            while (*(volatile unsigned*)&g_sense == snap) __nanosleep(32);
        }
        __threadfence();                              // acquire
    }
    __syncthreads();

    // ================ phase 2: per-tile stats (warps 0-3) ===================
    const int lane = tid & 31;
    if (tyb < TILES_PER_BLOCK) {
        const int tidx = bid + tyb * GRIDP;
        const int c    = (tidx / 9) & (Cn - 1);
        float s = __ldcg(&g_psum[c * NPART + lane]);
        float q = __ldcg(&g_psq [c * NPART + lane]);
        if (lane < NPART - 32) {
            s += __ldcg(&g_psum[c * NPART + lane + 32]);
            q += __ldcg(&g_psq [c * NPART + lane + 32]);
        }
        #pragma unroll
        for (int o = 16; o > 0; o >>= 1) {
            s += __shfl_xor_sync(0xffffffffu, s, o);
            q += __shfl_xor_sync(0xffffffffu, q, o);
        }
        if (lane == 0) {
            const float invN = 1.0f / (float)CNT_PER_CH;
            float mean = s * invN;
            float var  = q * invN - mean * mean;
            float scl  = rsqrtf(var + BN_EPS) * gamma[c];
            s_bn[tyb] = make_float2(scl, fmaf(-mean, scl, beta[c]));
        }
    }
    __syncthreads();

    // ================ phase 3: BN + ReLU from smem, float4 out ==============
    // thread t handles float4 element t of each 1024-float tile:
    //  row = t/8, col4 = t%8
    const int row  = tid >> 3;
    const int col4 = (tid & 7) * 4;
    #pragma unroll
    for (int it = 0; it < TILES_PER_BLOCK; it++) {
        const int tidx  = bid + it * GRIDP;
        const int plane = tidx / 9;
        const int tq    = tidx % 9;
        const int ty0   = (tq / 3) * 32;
        const int tx0   = (tq % 3) * 32;
        const float2 bn = s_bn[it];

        float4 v = *reinterpret_cast<const float4*>(&s_y[it][row * 32 + col4]);
        float4 o;
        o.x = fmaxf(fmaf(v.x, bn.x, bn.y), 0.0f);
        o.y = fmaxf(fmaf(v.y, bn.x, bn.y), 0.0f);
        o.z = fmaxf(fmaf(v.z, bn.x, bn.y), 0.0f);
        o.w = fmaxf(fmaf(v.w, bn.x, bn.y), 0.0f);
        *reinterpret_cast<float4*>(&out[plane * PLANE + (ty0 + row) * Wn + tx0 + col4]) = o;
    }
}

// ---------------------------------------------------------------------------
extern "C" void kernel_launch(void* const* d_in, const int* in_sizes, int n_in,
                              void* d_out, int out_size)
{
    const float* x             = (const float*)d_in[0];
    const float* base_weight   = (const float*)d_in[1];
    const float* spline_weight = (const float*)d_in[2];
    const float* spline_scaler = (const float*)d_in[3];
    const float* bn_gamma      = (const float*)d_in[4];
    const float* bn_beta       = (const float*)d_in[5];
    float* out                 = (float*)d_out;

    kan_fused_kernel<<<GRIDP, 256>>>(x, base_weight, spline_weight, spline_scaler,
                                     bn_gamma, bn_beta, out);
}

// round 7
// speedup vs baseline: 1.0708x; 1.0708x over previous
#include <cuda_runtime.h>
#include <cuda_fp16.h>
#include <cuda_bf16.h>

// Problem constants
#define Bn 4
#define Cn 64
#define Hn 96
#define Wn 96
#define PLANE (Hn*Wn)            // 9216
#define NPLANES (Bn*Cn)          // 256
#define NTOT (NPLANES*PLANE)     // 2359296
#define CNT_PER_CH (Bn*PLANE)    // 36864
#define BN_EPS 1e-5f
#define NPART 36                 // partial sums per channel: Bn * (3x3 blocks)

// Scratch (__device__ globals; allocation-free rule)
__device__ float g_y[NTOT];
__device__ float g_psum[Cn * NPART];
__device__ float g_psq [Cn * NPART];

// ---------------------------------------------------------------------------
// Kernel 1: fused KAN depthwise conv + race-free per-channel partial sums
// grid = (3, 3, 256 planes), block = 256 threads (32 x 8), 4 rows/thread.
// Transform stage fully decodes each element: (silu, u) + coef-row byte
// offset. Inner loop has NO float<->int conversions on the critical path.
// ---------------------------------------------------------------------------
__global__ __launch_bounds__(256)
void kan_conv_kernel(const float* __restrict__ x,
                     const float* __restrict__ base_weight,    // (9)
                     const float* __restrict__ spline_weight,  // (9,8)
                     const float* __restrict__ spline_scaler)  // (9)
{
    __shared__ float2 s_su[34 * 35];       // (silu, u) tile with halo, pitch 35
    __shared__ int    s_mo[34 * 35];       // coef row byte offset = m * 72
    __shared__ uint2  s_coef[12 * 9];      // half2(c0,c1), half2(c2,c3)
    __shared__ float  s_bw[9];
    __shared__ float  s_rs[8], s_rq[8];

    const int tid   = threadIdx.x;
    const int plane = blockIdx.z;
    const int ty0   = blockIdx.y * 32;
    const int tx0   = blockIdx.x * 32;

    // ---- build coefficient table (uniform cubic B-spline, closed form) ----
    if (tid < 108) {
        const int m = tid / 9, k = tid % 9;
        float c0 = 0.f, c1 = 0.f, c2 = 0.f, c3 = 0.f;
        if (m < 11) {
            const float F[4][4] = {
                {1.f, -3.f,  3.f, -1.f},   // N_{m-3}
                {4.f,  0.f, -6.f,  3.f},   // N_{m-2}
                {1.f,  3.f,  3.f, -3.f},   // N_{m-1}
                {0.f,  0.f,  0.f,  1.f}    // N_{m}
            };
            const float sc = spline_scaler[k];
            #pragma unroll
            for (int r = 0; r < 4; r++) {
                int j = m - 3 + r;
                if (j >= 0 && j < 8) {
                    float w = spline_weight[k * 8 + j] * sc;
                    c0 += w * F[r][0]; c1 += w * F[r][1];
                    c2 += w * F[r][2]; c3 += w * F[r][3];
                }
            }
        }
        const float inv6 = 1.0f / 6.0f;
        __half2 h01 = __floats2half2_rn(c0 * inv6, c1 * inv6);
        __half2 h23 = __floats2half2_rn(c2 * inv6, c3 * inv6);
        uint2 w;
        w.x = *reinterpret_cast<unsigned*>(&h01);
        w.y = *reinterpret_cast<unsigned*>(&h23);
        s_coef[m * 9 + k] = w;
    }
    if (tid < 9) s_bw[tid] = base_weight[tid];

    // ---- load + transform + decode halo tile (34x34) ----
    const float* xp = x + plane * PLANE;
    for (int i = tid; i < 34 * 34; i += 256) {
        int hy = i / 34, hx = i % 34;
        int gy = ty0 + hy - 1, gx = tx0 + hx - 1;
        float v = (gy >= 0 && gy < Hn && gx >= 0 && gx < Wn) ? xp[gy * Wn + gx] : 0.0f;
        float s  = __fdividef(v, 1.0f + __expf(-v));   // silu
        float mu = (v + 2.2f) * 2.5f;                  // (x - t0)/h
        if (!(mu >= 0.0f && mu < 11.0f)) mu = 11.0f;   // sentinel -> zero row
        int   m = (int)mu;
        float u = mu - (float)m;
        const int idx = hy * 35 + hx;
        s_su[idx] = make_float2(s, u);
        s_mo[idx] = m * 72;                            // row m of s_coef (9 * 8B)
    }
    __syncthreads();

    // ---- compute 32x32 outputs (4 strided rows per thread) ----
    const int tx  = tid & 31;
    const int tyb = tid >> 5;
    float lsum = 0.f, lsq = 0.f;
    const char* cbase = (const char*)s_coef;

    #pragma unroll
    for (int r = 0; r < 4; r++) {
        const int oy = tyb + r * 8;
        float acc = 0.f;
        #pragma unroll
        for (int dy = 0; dy < 3; dy++) {
            #pragma unroll
            for (int dx = 0; dx < 3; dx++) {
                const int k   = dy * 3 + dx;
                const int idx = (oy + dy) * 35 + (tx + dx);
                float2 t  = s_su[idx];
                int    mo = s_mo[idx];
                uint2  cw = *(const uint2*)(cbase + mo + k * 8);
                float2 c01 = __half22float2(*reinterpret_cast<__half2*>(&cw.x));
                float2 c23 = __half22float2(*reinterpret_cast<__half2*>(&cw.y));
                float poly = fmaf(t.y, fmaf(t.y, fmaf(t.y, c23.y, c23.x), c01.y), c01.x);
                acc += poly + s_bw[k] * t.x;
            }
        }
        g_y[plane * PLANE + (ty0 + oy) * Wn + (tx0 + tx)] = acc;
        lsum += acc;
        lsq  = fmaf(acc, acc, lsq);
    }

    // ---- block reduction -> race-free partial slot ----
    #pragma unroll
    for (int o = 16; o > 0; o >>= 1) {
        lsum += __shfl_down_sync(0xffffffffu, lsum, o);
        lsq  += __shfl_down_sync(0xffffffffu, lsq,  o);
    }
    if (tx == 0) { s_rs[tyb] = lsum; s_rq[tyb] = lsq; }
    __syncthreads();
    if (tid == 0) {
        float s = 0.f, q = 0.f;
        #pragma unroll
        for (int i = 0; i < 8; i++) { s += s_rs[i]; q += s_rq[i]; }
        const int c = plane & (Cn - 1);
        const int b = plane >> 6;
        const int slot = c * NPART + b * 9 + blockIdx.y * 3 + blockIdx.x;
        g_psum[slot] = s;
        g_psq [slot] = q;
    }
}

// ---------------------------------------------------------------------------
// Kernel 2: BatchNorm (batch stats from partials) + ReLU
// grid = (3, 256 planes), block = 256; 3 float4 per thread; per-warp
// redundant butterfly stats (no smem, no __syncthreads).
// ---------------------------------------------------------------------------
__global__ __launch_bounds__(256)
void bn_relu_kernel(const float* __restrict__ gamma,
                    const float* __restrict__ beta,
                    float* __restrict__ out)
{
    const int plane = blockIdx.y;
    const int c     = plane & (Cn - 1);
    const int tid   = threadIdx.x;
    const int lane  = tid & 31;

    // start the stats chain FIRST (it is the critical path)
    float s = g_psum[c * NPART + lane % NPART];
    float q = g_psq [c * NPART + lane % NPART];

    // then issue the 3 independent data loads
    const int base = plane * (PLANE / 4) + blockIdx.x * 768 + tid;
    float4 v0 = reinterpret_cast<const float4*>(g_y)[base];
    float4 v1 = reinterpret_cast<const float4*>(g_y)[base + 256];
    float4 v2 = reinterpret_cast<const float4*>(g_y)[base + 512];

    if (lane < NPART - 32) {
        s += g_psum[c * NPART + lane + 32];
        q += g_psq [c * NPART + lane + 32];
    }
    #pragma unroll
    for (int o = 16; o > 0; o >>= 1) {
        s += __shfl_xor_sync(0xffffffffu, s, o);
        q += __shfl_xor_sync(0xffffffffu, q, o);
    }

    const float invN = 1.0f / (float)CNT_PER_CH;
    float mean = s * invN;
    float var  = q * invN - mean * mean;
    float scl  = rsqrtf(var + BN_EPS) * gamma[c];
    float sh   = fmaf(-mean, scl, beta[c]);

    float4 o0, o1, o2;
    o0.x = fmaxf(fmaf(v0.x, scl, sh), 0.0f);
    o0.y = fmaxf(fmaf(v0.y, scl, sh), 0.0f);
    o0.z = fmaxf(fmaf(v0.z, scl, sh), 0.0f);
    o0.w = fmaxf(fmaf(v0.w, scl, sh), 0.0f);
    o1.x = fmaxf(fmaf(v1.x, scl, sh), 0.0f);
    o1.y = fmaxf(fmaf(v1.y, scl, sh), 0.0f);
    o1.z = fmaxf(fmaf(v1.z, scl, sh), 0.0f);
    o1.w = fmaxf(fmaf(v1.w, scl, sh), 0.0f);
    o2.x = fmaxf(fmaf(v2.x, scl, sh), 0.0f);
    o2.y = fmaxf(fmaf(v2.y, scl, sh), 0.0f);
    o2.z = fmaxf(fmaf(v2.z, scl, sh), 0.0f);
    o2.w = fmaxf(fmaf(v2.w, scl, sh), 0.0f);
    reinterpret_cast<float4*>(out)[base]       = o0;
    reinterpret_cast<float4*>(out)[base + 256] = o1;
    reinterpret_cast<float4*>(out)[base + 512] = o2;
}

// ---------------------------------------------------------------------------
extern "C" void kernel_launch(void* const* d_in, const int* in_sizes, int n_in,
                              void* d_out, int out_size)
{
    const float* x             = (const float*)d_in[0];
    const float* base_weight   = (const float*)d_in[1];
    const float* spline_weight = (const float*)d_in[2];
    const float* spline_scaler = (const float*)d_in[3];
    const float* bn_gamma      = (const float*)d_in[4];
    const float* bn_beta       = (const float*)d_in[5];
    float* out                 = (float*)d_out;

    dim3 grid(3, 3, NPLANES);
    kan_conv_kernel<<<grid, 256>>>(x, base_weight, spline_weight, spline_scaler);

    dim3 bgrid(3, NPLANES);   // 768 blocks, 3 float4 per thread
    bn_relu_kernel<<<bgrid, 256>>>(bn_gamma, bn_beta, out);
}